// round 17
// baseline (speedup 1.0000x reference)
#include <cuda_runtime.h>
#include <cuda_bf16.h>
#include <cuda_fp16.h>
#include <cstdint>

// ---------------------------------------------------------------------------
// Problem constants
// ---------------------------------------------------------------------------
#define Bb 4
#define Cc 256
#define VC 128
#define NT 4096          // H*W
#define BM 128           // queries per CTA
#define BN 64            // keys per tile
#define NTILES (NT / BN) // 64
#define LOG2E 1.4426950408889634f

// Scratch
__device__ __nv_bfloat16 g_xhi[Bb * NT * Cc];   // x split, [b][n][c]
__device__ __nv_bfloat16 g_xlo[Bb * NT * Cc];
__device__ __nv_bfloat16 g_Whi[3 * VC * Cc];    // W split, [wi][d][c]
__device__ __nv_bfloat16 g_Wlo[3 * VC * Cc];
__device__ __half        g_Q  [Bb * NT * VC];   // Q*log2e fp16, [b][n][d]
__device__ __half        g_K  [Bb * NT * VC];   // K fp16, [b][n][d]
__device__ __half        g_V  [Bb * VC * NT];   // V fp16, [b][d][n]

// ---------------------------------------------------------------------------
// helpers
// ---------------------------------------------------------------------------
__device__ __forceinline__ uint32_t smem_u32(const void* p) {
    uint32_t a;
    asm("{ .reg .u64 t; cvta.to.shared.u64 t, %1; cvt.u32.u64 %0, t; }"
        : "=r"(a) : "l"(p));
    return a;
}
__device__ __forceinline__ float ex2(float x) {
    float y;
    asm("ex2.approx.ftz.f32 %0, %1;" : "=f"(y) : "f"(x));
    return y;
}
// packed fp16 exp2: input half2, output half2 (single MUFU op for 2 values)
__device__ __forceinline__ uint32_t ex2_h2(uint32_t x) {
    uint32_t y;
    asm("ex2.approx.f16x2 %0, %1;" : "=r"(y) : "r"(x));
    return y;
}
// pack two floats to half2: d.lo = lo, d.hi = hi
__device__ __forceinline__ uint32_t cvt_h2(float hi, float lo) {
    uint32_t d;
    asm("cvt.rn.f16x2.f32 %0, %1, %2;" : "=r"(d) : "f"(hi), "f"(lo));
    return d;
}

#define CP_ASYNC16(dst, src) \
    asm volatile("cp.async.cg.shared.global [%0], [%1], 16;" \
                 :: "r"(dst), "l"(src) : "memory")
#define CP_COMMIT() asm volatile("cp.async.commit_group;" ::: "memory")
#define CP_WAIT1()  asm volatile("cp.async.wait_group 1;" ::: "memory")
#define CP_WAIT0()  asm volatile("cp.async.wait_group 0;" ::: "memory")

__device__ __forceinline__ void ldsm_x4(uint32_t addr, uint32_t& r0, uint32_t& r1,
                                        uint32_t& r2, uint32_t& r3) {
    asm volatile("ldmatrix.sync.aligned.m8n8.x4.shared.b16 {%0,%1,%2,%3}, [%4];"
                 : "=r"(r0), "=r"(r1), "=r"(r2), "=r"(r3) : "r"(addr));
}

__device__ __forceinline__ void mma_bf16(float* c, const uint32_t a[4],
                                         uint32_t b0, uint32_t b1) {
    asm volatile(
        "mma.sync.aligned.m16n8k16.row.col.f32.bf16.bf16.f32 "
        "{%0,%1,%2,%3}, {%4,%5,%6,%7}, {%8,%9}, {%0,%1,%2,%3};"
        : "+f"(c[0]), "+f"(c[1]), "+f"(c[2]), "+f"(c[3])
        : "r"(a[0]), "r"(a[1]), "r"(a[2]), "r"(a[3]), "r"(b0), "r"(b1));
}
__device__ __forceinline__ void mma_f16(float* c, const uint32_t a[4],
                                        uint32_t b0, uint32_t b1) {
    asm volatile(
        "mma.sync.aligned.m16n8k16.row.col.f32.f16.f16.f32 "
        "{%0,%1,%2,%3}, {%4,%5,%6,%7}, {%8,%9}, {%0,%1,%2,%3};"
        : "+f"(c[0]), "+f"(c[1]), "+f"(c[2]), "+f"(c[3])
        : "r"(a[0]), "r"(a[1]), "r"(a[2]), "r"(a[3]), "r"(b0), "r"(b1));
}

__device__ __forceinline__ void split_bf(float v, __nv_bfloat16& h, __nv_bfloat16& l) {
    h = __float2bfloat16_rn(v);
    l = __float2bfloat16_rn(v - __bfloat162float(h));
}
__device__ __forceinline__ uint32_t pk(__nv_bfloat16 a, __nv_bfloat16 b) {
    __nv_bfloat162 t = __halves2bfloat162(a, b);
    uint32_t u;
    *reinterpret_cast<__nv_bfloat162*>(&u) = t;
    return u;
}
__device__ __forceinline__ uint32_t pkh(__half a, __half b) {
    __half2 t = __halves2half2(a, b);
    uint32_t u;
    *reinterpret_cast<__half2*>(&u) = t;
    return u;
}

// swizzled byte offsets: 256B rows (16 chunks of 16B), 128B rows (8 chunks)
__device__ __forceinline__ uint32_t swz_q(int row, int ch) {
    return (uint32_t)(row * 256 + ((ch ^ (row & 7)) << 4));
}
__device__ __forceinline__ uint32_t swz_v(int row, int ch) {
    return (uint32_t)(row * 128 + ((ch ^ (row & 7)) << 4));
}

// ---------------------------------------------------------------------------
// W split: Wq/Wk/Wv [d][c] fp32 -> g_Whi/g_Wlo bf16 [wi][d][c]
// ---------------------------------------------------------------------------
__global__ __launch_bounds__(256) void wsplit_kernel(
    const float* __restrict__ Wq,
    const float* __restrict__ Wk,
    const float* __restrict__ Wv)
{
    const int idx = blockIdx.x * 256 + threadIdx.x;
    const int f0  = idx * 4;
    const int wi  = f0 / (VC * Cc);
    const int off = f0 - wi * (VC * Cc);
    const float* W = (wi == 0) ? Wq : (wi == 1) ? Wk : Wv;
    float4 v = *(const float4*)(W + off);
    __nv_bfloat16 h0, l0, h1, l1, h2, l2, h3, l3;
    split_bf(v.x, h0, l0); split_bf(v.y, h1, l1);
    split_bf(v.z, h2, l2); split_bf(v.w, h3, l3);
    size_t o = (size_t)wi * VC * Cc + off;
    *(uint2*)(g_Whi + o) = make_uint2(pk(h0, h1), pk(h2, h3));
    *(uint2*)(g_Wlo + o) = make_uint2(pk(l0, l1), pk(l2, l3));
}

// ---------------------------------------------------------------------------
// x split/transpose: x [b][c][n] fp32 -> g_xhi/g_xlo [b][n][c] bf16.
// ---------------------------------------------------------------------------
__global__ __launch_bounds__(256) void xsplit_kernel(const float* __restrict__ x)
{
    __shared__ float T[64][65];
    const int b  = blockIdx.z;
    const int c0 = blockIdx.y * 64;
    const int n0 = blockIdx.x * 64;
    const int tid = threadIdx.x;

    #pragma unroll
    for (int i = tid; i < 64 * 16; i += 256) {
        int c = i >> 4, n4 = i & 15;
        float4 v = *(const float4*)(x + ((size_t)b * Cc + c0 + c) * NT + n0 + n4 * 4);
        T[c][n4 * 4 + 0] = v.x; T[c][n4 * 4 + 1] = v.y;
        T[c][n4 * 4 + 2] = v.z; T[c][n4 * 4 + 3] = v.w;
    }
    __syncthreads();
    #pragma unroll
    for (int i = tid; i < 64 * 32; i += 256) {
        int n = i >> 5, c2 = i & 31;
        float f0 = T[c2 * 2][n], f1 = T[c2 * 2 + 1][n];
        __nv_bfloat16 h0, l0, h1, l1;
        split_bf(f0, h0, l0);
        split_bf(f1, h1, l1);
        size_t off = ((size_t)b * NT + n0 + n) * Cc + c0 + c2 * 2;
        *(uint32_t*)(g_xhi + off) = pk(h0, h1);
        *(uint32_t*)(g_xlo + off) = pk(l0, l1);
    }
}

// ---------------------------------------------------------------------------
// Fused QKV projection (split-bf16, 3-pass). A staged once, B double-buffered.
// Epilogue: Q -> fp16 (scaled log2e), K -> fp16, V -> fp16 [b][d][n].
// grid (NT/128, Bb), 256 threads, smem 192KB.
// ---------------------------------------------------------------------------
#define FA_OFF(kc, comp) (((kc) * 2 + (comp)) * 16384)
#define FB_OFF 131072
#define FB_BUF 32768
#define PF_SMEM 196608

extern __shared__ char proj_sm[];

__device__ __forceinline__ void proj_load_B(uint32_t sb, int wi, int kc, int buf, int tid)
{
    #pragma unroll
    for (int i = tid; i < 2048; i += 256) {
        int comp = i >> 10, row = (i >> 3) & 127, ch = i & 7;
        const __nv_bfloat16* src = comp ? g_Wlo : g_Whi;
        const char* g = (const char*)(src + (size_t)wi * VC * Cc + (size_t)row * Cc + kc * 64)
                        + ch * 16;
        CP_ASYNC16(sb + FB_OFF + buf * FB_BUF + comp * 16384 + swz_v(row, ch), g);
    }
}

__global__ __launch_bounds__(256, 1) void proj_fused_kernel()
{
    const int b  = blockIdx.y;
    const int n0 = blockIdx.x * 128;

    const int tid  = threadIdx.x;
    const int w    = tid >> 5;
    const int lane = tid & 31;
    const int q0   = w * 16;

    char* psm = proj_sm;
    const uint32_t sb = smem_u32(psm);

    const int a_row = q0 + (lane & 15);
    const int a_c16 = lane >> 4;
    const int b_row = (lane & 7) + ((lane >> 4) << 3);
    const int b_ch  = (lane >> 3) & 1;

    #pragma unroll
    for (int i = tid; i < 8192; i += 256) {
        int comp = i >> 12;
        int rem  = i & 4095;
        int kc   = rem >> 10;
        int row  = (rem >> 3) & 127;
        int ch   = rem & 7;
        const __nv_bfloat16* src = comp ? g_xlo : g_xhi;
        const char* g = (const char*)(src + ((size_t)b * NT + n0 + row) * Cc + kc * 64)
                        + ch * 16;
        CP_ASYNC16(sb + FA_OFF(kc, comp) + swz_v(row, ch), g);
    }
    proj_load_B(sb, 0, 0, 0, tid);
    CP_COMMIT();

    float C[16][4];
    const int r  = lane >> 2;
    const int cq = (lane & 3) * 2;

    #pragma unroll 1
    for (int it = 0; it < 12; it++) {
        const int wi  = it >> 2;
        const int kc  = it & 3;
        const int buf = it & 1;

        if (kc == 0) {
            #pragma unroll
            for (int i = 0; i < 16; i++)
                #pragma unroll
                for (int j = 0; j < 4; j++) C[i][j] = 0.f;
        }

        __syncthreads();
        if (it + 1 < 12) {
            proj_load_B(sb, (it + 1) >> 2, (it + 1) & 3, buf ^ 1, tid);
            CP_COMMIT();
            CP_WAIT1();
        } else {
            CP_WAIT0();
        }
        __syncthreads();

        const uint32_t bh_base = sb + FB_OFF + buf * FB_BUF;
        const uint32_t bl_base = bh_base + 16384;
        const uint32_t ah_base = sb + FA_OFF(kc, 0);
        const uint32_t al_base = sb + FA_OFF(kc, 1);

        #pragma unroll
        for (int kk = 0; kk < 4; kk++) {
            uint32_t ah[4], al[4];
            ldsm_x4(ah_base + swz_v(a_row, 2 * kk + a_c16), ah[0], ah[1], ah[2], ah[3]);
            ldsm_x4(al_base + swz_v(a_row, 2 * kk + a_c16), al[0], al[1], al[2], al[3]);
            #pragma unroll
            for (int nt = 0; nt < 8; nt++) {
                uint32_t bh0, bh1, bh2, bh3, bl0, bl1, bl2, bl3;
                ldsm_x4(bh_base + swz_v(nt * 16 + b_row, 2 * kk + b_ch), bh0, bh1, bh2, bh3);
                ldsm_x4(bl_base + swz_v(nt * 16 + b_row, 2 * kk + b_ch), bl0, bl1, bl2, bl3);
                mma_bf16(C[2 * nt],     ah, bh0, bh1);
                mma_bf16(C[2 * nt + 1], ah, bh2, bh3);
                mma_bf16(C[2 * nt],     ah, bl0, bl1);
                mma_bf16(C[2 * nt + 1], ah, bl2, bl3);
                mma_bf16(C[2 * nt],     al, bh0, bh1);
                mma_bf16(C[2 * nt + 1], al, bh2, bh3);
            }
        }

        if (kc == 3) {
            if (wi < 2) {
                // Q (scaled by log2e) or K -> single fp16 [b][n][d]
                __half* dst = (wi == 0) ? g_Q : g_K;
                const float sc = (wi == 0) ? LOG2E : 1.0f;
                #pragma unroll
                for (int nt = 0; nt < 16; nt++) {
                    int d = nt * 8 + cq;
                    size_t o0 = ((size_t)b * NT + n0 + q0 + r) * VC + d;
                    *(uint32_t*)(dst + o0) = pkh(__float2half_rn(C[nt][0] * sc),
                                                 __float2half_rn(C[nt][1] * sc));
                    size_t o1 = o0 + (size_t)8 * VC;
                    *(uint32_t*)(dst + o1) = pkh(__float2half_rn(C[nt][2] * sc),
                                                 __float2half_rn(C[nt][3] * sc));
                }
            } else {
                float* Vt = (float*)psm;   // 64 x 132 floats
                #pragma unroll
                for (int h = 0; h < 2; h++) {
                    __syncthreads();
                    #pragma unroll
                    for (int nt = h * 8; nt < h * 8 + 8; nt++) {
                        int dl = nt * 8 + cq - h * 64;
                        Vt[dl * 132 + q0 + r]           = C[nt][0];
                        Vt[(dl + 1) * 132 + q0 + r]     = C[nt][1];
                        Vt[dl * 132 + q0 + r + 8]       = C[nt][2];
                        Vt[(dl + 1) * 132 + q0 + r + 8] = C[nt][3];
                    }
                    __syncthreads();
                    #pragma unroll
                    for (int i = tid; i < 64 * 64; i += 256) {
                        int dd = i >> 6, n2 = i & 63;
                        __half2 hv = __floats2half2_rn(Vt[dd * 132 + n2 * 2],
                                                       Vt[dd * 132 + n2 * 2 + 1]);
                        *(__half2*)(g_V + ((size_t)b * VC + h * 64 + dd) * NT + n0 + n2 * 2) = hv;
                    }
                }
            }
        }
    }
}

// ---------------------------------------------------------------------------
// Flash attention: fp16 single-pass S + fp16 single-pass PV with a ones-column
// in V (tensor-core rowsum in O[16]); ex2.approx.f16x2 softmax interleaved
// with PV issue; online-max (base-2).
// smem: Q 0 (32K), K[2] 32K (16K bufs), V[2] 64K (20K strides, 144 rows:
//   rows 0..127 = data (refilled per tile), row 128 = ones, 129..143 = 0,
//   the static rows written once at kernel start).
// ---------------------------------------------------------------------------
#define Q_OFF   0
#define K_OFF   32768
#define V_OFF   65536
#define KBUF 16384
#define VBUF 20480
#define S_TOTAL (65536 + 2 * 20480)   // 106496

extern __shared__ char fa_sm[];

__device__ __forceinline__ void load_kv(uint32_t sbase, int b, int t, int buf, int tid)
{
    const int k0 = t * BN;
    // K fp16: 64 rows x 16 chunks of 16B
    {
        uint32_t dst = sbase + K_OFF + buf * KBUF;
        #pragma unroll
        for (int i = tid; i < 64 * 16; i += 256) {
            int row = i >> 4, ch = i & 15;
            const char* g = (const char*)(g_K + ((size_t)b * NT + k0 + row) * VC) + ch * 16;
            CP_ASYNC16(dst + swz_q(row, ch), g);
        }
    }
    // V: 128 d-rows x 8 chunks (64 keys); rows 128..143 are static (not touched)
    {
        uint32_t dst = sbase + V_OFF + buf * VBUF;
        #pragma unroll
        for (int i = tid; i < 128 * 8; i += 256) {
            int row = i >> 3, ch = i & 7;
            const char* g = (const char*)(g_V + ((size_t)b * VC + row) * NT + k0) + ch * 16;
            CP_ASYNC16(dst + swz_v(row, ch), g);
        }
    }
}

__global__ __launch_bounds__(256, 1) void fa_kernel(float* __restrict__ out)
{
    const int tid  = threadIdx.x;
    const int w    = tid >> 5;
    const int lane = tid & 31;
    const int b    = blockIdx.y;
    const int n0   = blockIdx.x * BM;
    const int q0   = w * 16;

    char* sm = fa_sm;
    const uint32_t sbase = smem_u32(sm);

    // static V rows 128..143 for BOTH buffers: row 128 = 1.0h, 129..143 = 0
    #pragma unroll
    for (int i = tid; i < 2 * 16 * 8; i += 256) {
        int buf = i >> 7, row = 128 + ((i >> 3) & 15), ch = i & 7;
        uint32_t val = (row == 128) ? 0x3C003C00u : 0u;
        uint4 v4 = make_uint4(val, val, val, val);
        *(uint4*)(sm + V_OFF + buf * VBUF + swz_v(row, ch)) = v4;
    }

    // stage Q (fp16)
    #pragma unroll
    for (int i = tid; i < 128 * 16; i += 256) {
        int row = i >> 4, ch = i & 15;
        const char* g = (const char*)(g_Q + ((size_t)b * NT + n0 + row) * VC) + ch * 16;
        CP_ASYNC16(sbase + Q_OFF + swz_q(row, ch), g);
    }
    load_kv(sbase, b, 0, 0, tid);
    CP_COMMIT();

    // O[0..15]: output d 0..127; O[16]: rowsum column (d=128 of ones-extended V)
    float O[17][4];
    #pragma unroll
    for (int i = 0; i < 17; i++)
        #pragma unroll
        for (int j = 0; j < 4; j++) O[i][j] = 0.f;
    float M0 = -1e30f, M1 = -1e30f;

    const int a_row = q0 + (lane & 15);
    const int a_ch  = (lane >> 4);
    const int b_row = (lane & 7) + ((lane >> 4) << 3);
    const int b_ch  = ((lane >> 3) & 1);

    #pragma unroll 1
    for (int t = 0; t < NTILES; t++) {
        const int buf = t & 1;
        if (t + 1 < NTILES) load_kv(sbase, b, t + 1, buf ^ 1, tid);
        CP_COMMIT();
        CP_WAIT1();
        __syncthreads();

        const uint32_t k_base = sbase + K_OFF + buf * KBUF;
        const uint32_t v_base = sbase + V_OFF + buf * VBUF;

        // ---- S = Q K^T: fp16 single pass, base-2 logits (Q pre-scaled) ----
        float C[8][4];
        #pragma unroll
        for (int i = 0; i < 8; i++)
            #pragma unroll
            for (int j = 0; j < 4; j++) C[i][j] = 0.f;

        #pragma unroll
        for (int kc = 0; kc < 8; kc++) {
            uint32_t aq[4];
            ldsm_x4(sbase + Q_OFF + swz_q(a_row, 2 * kc + a_ch),
                    aq[0], aq[1], aq[2], aq[3]);
            #pragma unroll
            for (int ntp = 0; ntp < 4; ntp++) {
                uint32_t k0r, k1r, k2r, k3r;
                ldsm_x4(k_base + swz_q(ntp * 16 + b_row, 2 * kc + b_ch),
                        k0r, k1r, k2r, k3r);
                mma_f16(C[2 * ntp],     aq, k0r, k1r);
                mma_f16(C[2 * ntp + 1], aq, k2r, k3r);
            }
        }

        // ---- row max + rescale (rowsum column rescales with O) ----
        float tm0 = -1e30f, tm1 = -1e30f;
        #pragma unroll
        for (int nt = 0; nt < 8; nt++) {
            tm0 = fmaxf(tm0, fmaxf(C[nt][0], C[nt][1]));
            tm1 = fmaxf(tm1, fmaxf(C[nt][2], C[nt][3]));
        }
        tm0 = fmaxf(tm0, __shfl_xor_sync(0xffffffffu, tm0, 1));
        tm0 = fmaxf(tm0, __shfl_xor_sync(0xffffffffu, tm0, 2));
        tm1 = fmaxf(tm1, __shfl_xor_sync(0xffffffffu, tm1, 1));
        tm1 = fmaxf(tm1, __shfl_xor_sync(0xffffffffu, tm1, 2));
        const float M0n = fmaxf(M0, tm0);
        const float M1n = fmaxf(M1, tm1);
        const float s0 = ex2(M0 - M0n);
        const float s1 = ex2(M1 - M1n);
        M0 = M0n; M1 = M1n;

        if (!__all_sync(0xffffffffu, (s0 == 1.0f) & (s1 == 1.0f))) {
            #pragma unroll
            for (int nt = 0; nt < 17; nt++) {
                O[nt][0] *= s0; O[nt][1] *= s0;
                O[nt][2] *= s1; O[nt][3] *= s1;
            }
        }

        // ---- interleaved: per kc group, f16x2 softmax then PV mma ----
        #pragma unroll
        for (int kc = 0; kc < 4; kc++) {
            uint32_t aph[4];
            {
                const int nt = 2 * kc;
                aph[0] = ex2_h2(cvt_h2(C[nt][1] - M0,     C[nt][0] - M0));
                aph[1] = ex2_h2(cvt_h2(C[nt][3] - M1,     C[nt][2] - M1));
                aph[2] = ex2_h2(cvt_h2(C[nt + 1][1] - M0, C[nt + 1][0] - M0));
                aph[3] = ex2_h2(cvt_h2(C[nt + 1][3] - M1, C[nt + 1][2] - M1));
            }
            #pragma unroll
            for (int ntp = 0; ntp < 8; ntp++) {
                uint32_t v0, v1, v2, v3;
                ldsm_x4(v_base + swz_v(ntp * 16 + b_row, 2 * kc + b_ch),
                        v0, v1, v2, v3);
                mma_f16(O[2 * ntp],     aph, v0, v1);
                mma_f16(O[2 * ntp + 1], aph, v2, v3);
            }
            // ones-column (d=128): rowsum accumulates into O[16]
            {
                uint32_t v0, v1, v2, v3;
                ldsm_x4(v_base + swz_v(128 + b_row, 2 * kc + b_ch),
                        v0, v1, v2, v3);
                mma_f16(O[16], aph, v0, v1);
            }
        }
        __syncthreads();   // all warps done with buf before it is refilled
    }

    // ---- finalize: denominators from the rowsum column ----
    // lanes with (lane&3)==0 hold col 128: O[16][0] = rowsum(row r),
    // O[16][2] = rowsum(row r+8). Broadcast within each 4-lane row group.
    const float inv0 = 1.0f / __shfl_sync(0xffffffffu, O[16][0], lane & 28);
    const float inv1 = 1.0f / __shfl_sync(0xffffffffu, O[16][2], lane & 28);

    __syncthreads();
    float* Ot = (float*)sm;   // 128x132 floats (67584B) fits in smem
    const int r  = lane >> 2;
    const int cc = (lane & 3) * 2;
    #pragma unroll
    for (int nt = 0; nt < 16; nt++) {
        int d = nt * 8 + cc;
        Ot[d * 132 + q0 + r]           = O[nt][0] * inv0;
        Ot[(d + 1) * 132 + q0 + r]     = O[nt][1] * inv0;
        Ot[d * 132 + q0 + r + 8]       = O[nt][2] * inv1;
        Ot[(d + 1) * 132 + q0 + r + 8] = O[nt][3] * inv1;
    }
    __syncthreads();

    float* outb = out + (size_t)b * VC * NT;
    #pragma unroll
    for (int i = tid; i < VC * BM; i += 256) {
        int d = i >> 7, q = i & 127;
        outb[(size_t)d * NT + n0 + q] = Ot[d * 132 + q];
    }
}

// ---------------------------------------------------------------------------
extern "C" void kernel_launch(void* const* d_in, const int* in_sizes, int n_in,
                              void* d_out, int out_size)
{
    const float* x  = (const float*)d_in[0];
    const float* Wq = (const float*)d_in[1];
    const float* Wk = (const float*)d_in[2];
    const float* Wv = (const float*)d_in[3];
    float* out = (float*)d_out;

    wsplit_kernel<<<3 * VC * Cc / 4 / 256, 256>>>(Wq, Wk, Wv);

    dim3 g0(NT / 64, Cc / 64, Bb);
    xsplit_kernel<<<g0, 256>>>(x);

    cudaFuncSetAttribute(proj_fused_kernel, cudaFuncAttributeMaxDynamicSharedMemorySize, PF_SMEM);
    dim3 g1(NT / 128, Bb);
    proj_fused_kernel<<<g1, 256, PF_SMEM>>>();

    cudaFuncSetAttribute(fa_kernel, cudaFuncAttributeMaxDynamicSharedMemorySize, S_TOTAL);
    dim3 g2(NT / BM, Bb);
    fa_kernel<<<g2, 256, S_TOTAL>>>(out);
}